// round 8
// baseline (speedup 1.0000x reference)
#include <cuda_runtime.h>
#include <cstdint>

#define N_NODES 10000
#define N_EDGES 320000

// ---------------- scratch (device globals; allocation-free) ----------------
__device__ float g_h[N_NODES * 64];                 // 2.56 MB
__device__ float g_agg[(size_t)N_NODES * 576];      // 23 MB; fully overwritten by k_edge
__device__ int   g_count[N_NODES];                  // zeroed by k_scan after read
__device__ int   g_rowstart[N_NODES + 1];
__device__ int   g_cursor[N_NODES];
__device__ int   g_csr[N_EDGES];
__device__ int   g_send[N_EDGES];
__device__ uint2 g_wfrag[10496];                    // fragment-ordered tf32 weights (84KB)

// uint2 offsets into g_wfrag
#define U_W1 0
#define U_W2 256
#define U_W3 2304
#define U_W4 4352       // + chunk*2048

__device__ __forceinline__ float silu_f(float x) {
    return x / (1.f + __expf(-x));
}

__device__ __forceinline__ uint32_t f2tf32(float f) {
    uint32_t r;
    asm("cvt.rna.tf32.f32 %0, %1;" : "=r"(r) : "f"(f));
    return r;
}

__device__ __forceinline__ void mma_tf32(float acc[4], uint32_t a0, uint32_t a1,
                                         uint32_t a2, uint32_t a3,
                                         uint32_t b0, uint32_t b1) {
    asm volatile(
        "mma.sync.aligned.m16n8k8.row.col.f32.tf32.tf32.f32 "
        "{%0,%1,%2,%3}, {%4,%5,%6,%7}, {%8,%9}, {%0,%1,%2,%3};\n"
        : "+f"(acc[0]), "+f"(acc[1]), "+f"(acc[2]), "+f"(acc[3])
        : "r"(a0), "r"(a1), "r"(a2), "r"(a3), "r"(b0), "r"(b1));
}

// ---------------- launch 0: pre-convert weights into fragment order ----------------
__global__ void k_prep(const float* __restrict__ W1, const float* __restrict__ W2,
                       const float* __restrict__ W3, const float* __restrict__ W4) {
    int u = blockIdx.x * 256 + threadIdx.x;
    if (u >= 10496) return;
    const float* src; int rs, co, KK, local;
    if (u < 256)       { src = W1; rs = 64;  co = 0;   KK = 1; local = u; }
    else if (u < 2304) { src = W2; rs = 64;  co = 0;   KK = 8; local = u - 256; }
    else if (u < 4352) { src = W3; rs = 64;  co = 0;   KK = 8; local = u - 2304; }
    else if (u < 6400) { src = W4; rs = 192; co = 0;   KK = 8; local = u - 4352; }
    else if (u < 8448) { src = W4; rs = 192; co = 64;  KK = 8; local = u - 6400; }
    else               { src = W4; rs = 192; co = 128; KK = 8; local = u - 8448; }
    int lane = local & 31; int rest = local >> 5;
    int nt = rest & 3; rest >>= 2;
    int kk = rest % KK; int hb = rest / KK;
    int n = co + hb * 32 + nt * 8 + (lane >> 2);
    int k0 = kk * 8 + (lane & 3);
    g_wfrag[u] = make_uint2(f2tf32(src[(size_t)k0 * rs + n]),
                            f2tf32(src[(size_t)(k0 + 4) * rs + n]));
}

// ---------------- launch 1: edge count histogram + h = (nf @ W_up)/8 ----------------
__global__ __launch_bounds__(256) void k_count_h(const int* __restrict__ recv,
                                                 const float* __restrict__ nf,
                                                 const float* __restrict__ Wup) {
    __shared__ float sW[64 * 64];
    __shared__ float sN[8 * 64];
    int t = threadIdx.x;
    int e = blockIdx.x * 256 + t;
    atomicAdd(&g_count[recv[e]], 1);          // N_EDGES % 256 == 0

    for (int idx = t; idx < 1024; idx += 256)
        ((float4*)sW)[idx] = ((const float4*)Wup)[idx];
    int n0 = blockIdx.x * 8;                  // 1250 * 8 = 10000
    if (t < 128)
        ((float4*)sN)[t] = ((const float4*)(nf + (size_t)n0 * 64))[t];
    __syncthreads();

#pragma unroll
    for (int j = 0; j < 2; ++j) {
        int o = t + j * 256;
        int row = o >> 6, c = o & 63;
        float a0 = 0.f, a1 = 0.f;
#pragma unroll
        for (int k = 0; k < 64; k += 2) {
            a0 = fmaf(sN[row * 64 + k],     sW[k * 64 + c],       a0);
            a1 = fmaf(sN[row * 64 + k + 1], sW[(k + 1) * 64 + c], a1);
        }
        g_h[(size_t)(n0 + row) * 64 + c] = (a0 + a1) * 0.125f;
    }
}

// ---------------- launch 2: parallel exclusive scan (+ zero g_count) ----------------
__global__ __launch_bounds__(1024) void k_scan() {
    __shared__ int warpsum[32];
    int t = threadIdx.x, lane = t & 31, w = t >> 5;
    int base = t * 10;
    int c[10];
    int s = 0;
#pragma unroll
    for (int i = 0; i < 10; ++i) {
        int idx = base + i;
        c[i] = (idx < N_NODES) ? g_count[idx] : 0;
        s += c[i];
    }
    int pre = s;
#pragma unroll
    for (int d = 1; d < 32; d <<= 1) {
        int v = __shfl_up_sync(0xffffffffu, pre, d);
        if (lane >= d) pre += v;
    }
    if (lane == 31) warpsum[w] = pre;
    __syncthreads();
    if (w == 0) {
        int v = warpsum[lane];
#pragma unroll
        for (int d = 1; d < 32; d <<= 1) {
            int u = __shfl_up_sync(0xffffffffu, v, d);
            if (lane >= d) v += u;
        }
        warpsum[lane] = v;
    }
    __syncthreads();
    int wbase = (w > 0) ? warpsum[w - 1] : 0;
    int run = wbase + pre - s;
#pragma unroll
    for (int i = 0; i < 10; ++i) {
        int idx = base + i;
        if (idx < N_NODES) {
            g_rowstart[idx] = run;
            g_cursor[idx] = run;
            run += c[i];
            g_count[idx] = 0;
        }
    }
    if (t == 1023) g_rowstart[N_NODES] = warpsum[31];
}

// ---------------- launch 3: CSR fill ----------------
__global__ void k_fill(const int* __restrict__ recv, const int* __restrict__ send) {
    int e = blockIdx.x * blockDim.x + threadIdx.x;
    if (e < N_EDGES) {
        int r = recv[e];
        int pos = atomicAdd(&g_cursor[r], 1);
        g_csr[pos] = e;
        g_send[pos] = send[e];
    }
}

// ---------------- launch 4: node-per-warp fused MLP + SH + TP + store ----------------
// One warp per node; walks its CSR range in 16-row tiles; aggregates the node's
// 9x64 output in registers; single plain STG per node. No atomics, no barriers.

// 64-col layer: acc[j] over 8 n-tiles, K=64 (8 kk steps)
__device__ __forceinline__ void layer64(int base, const uint32_t A0[8],
                                        const uint32_t A1[8], const uint32_t A2[8],
                                        const uint32_t A3[8], float acc[8][4],
                                        int lane) {
#pragma unroll
    for (int j = 0; j < 8; ++j) {
        acc[j][0] = 0.f; acc[j][1] = 0.f; acc[j][2] = 0.f; acc[j][3] = 0.f;
    }
#pragma unroll
    for (int kk = 0; kk < 8; ++kk) {
#pragma unroll
        for (int j = 0; j < 8; ++j) {
            uint2 b = __ldg(&g_wfrag[base + ((j >> 2) * 32 + kk * 4 + (j & 3)) * 32 + lane]);
            mma_tf32(acc[j], A0[kk], A1[kk], A2[kk], A3[kk], b.x, b.y);
        }
    }
}

// C-frag -> next layer A-frag conversion (scale + silu + tf32), via shuffles.
__device__ __forceinline__ void cvt_frag(const float acc[8][4], float scale,
                                         uint32_t A0[8], uint32_t A1[8],
                                         uint32_t A2[8], uint32_t A3[8],
                                         int lane, int tid4) {
    int src  = (lane & 28) | (tid4 >> 1);
    int src2 = src + 2;
    bool odd = (tid4 & 1);
#pragma unroll
    for (int j = 0; j < 8; ++j) {
        uint32_t c0 = f2tf32(silu_f(acc[j][0] * scale));
        uint32_t c1 = f2tf32(silu_f(acc[j][1] * scale));
        uint32_t c2 = f2tf32(silu_f(acc[j][2] * scale));
        uint32_t c3 = f2tf32(silu_f(acc[j][3] * scale));
        uint32_t s0 = __shfl_sync(0xffffffffu, c0, src);
        uint32_t s1 = __shfl_sync(0xffffffffu, c1, src);
        uint32_t s2 = __shfl_sync(0xffffffffu, c2, src);
        uint32_t s3 = __shfl_sync(0xffffffffu, c3, src);
        uint32_t u0 = __shfl_sync(0xffffffffu, c0, src2);
        uint32_t u1 = __shfl_sync(0xffffffffu, c1, src2);
        uint32_t u2 = __shfl_sync(0xffffffffu, c2, src2);
        uint32_t u3 = __shfl_sync(0xffffffffu, c3, src2);
        A0[j] = odd ? s1 : s0;
        A1[j] = odd ? s3 : s2;
        A2[j] = odd ? u1 : u0;
        A3[j] = odd ? u3 : u2;
    }
}

template <int D, int KOFF>
__device__ __forceinline__ void l4_chunk(int base, const uint32_t A0[8],
                                         const uint32_t A1[8], const uint32_t A2[8],
                                         const uint32_t A3[8],
                                         int s0r, int s1r,
                                         float* __restrict__ wMsg,
                                         const float* __restrict__ wSh,
                                         float* __restrict__ na,
                                         float* __restrict__ nb,
                                         int lane, int gid, int tid4, int vcnt) {
    float acc[8][4];
    layer64(base, A0, A1, A2, A3, acc, lane);

    const float S = 1.f / 256.f;   // 1/sqrt(64) / avg_neigh
#pragma unroll
    for (int j = 0; j < 8; ++j) {
        int col = j * 8 + 2 * tid4;
        float2 h0 = *(const float2*)(g_h + (size_t)s0r * 64 + col);
        float2 h1 = *(const float2*)(g_h + (size_t)s1r * 64 + col);
        *(float2*)(wMsg + gid * 66 + col) =
            make_float2(acc[j][0] * h0.x * S, acc[j][1] * h0.y * S);
        *(float2*)(wMsg + (gid + 8) * 66 + col) =
            make_float2(acc[j][2] * h1.x * S, acc[j][3] * h1.y * S);
    }
    __syncwarp();

    // lane accumulates channels (lane) and (lane+32) over this tile's valid rows
    for (int r = 0; r < vcnt; ++r) {
        float m0 = wMsg[r * 66 + lane];
        float m1 = wMsg[r * 66 + 32 + lane];
#pragma unroll
        for (int k = 0; k < D; ++k) {
            float s = wSh[r * 12 + KOFF + k];
            na[KOFF + k] = fmaf(m0, s, na[KOFF + k]);
            nb[KOFF + k] = fmaf(m1, s, nb[KOFF + k]);
        }
    }
    __syncwarp();   // all lanes done reading wMsg before next chunk overwrites
}

__global__ __launch_bounds__(256, 2) void k_edge(const float* __restrict__ evec,
                                                 const float* __restrict__ rad) {
    __shared__ float sMsgAll[8][16 * 66];     // 33792 B
    __shared__ float sShAll[8][16 * 12];      // 6144 B

    int t = threadIdx.x, lane = t & 31, warp = t >> 5;
    int gid = lane >> 2, tid4 = lane & 3;
    float* wMsg = sMsgAll[warp];
    float* wSh  = sShAll[warp];

    int n = blockIdx.x * 8 + warp;
    int beg = g_rowstart[n], end = g_rowstart[n + 1];

    float na[9], nb[9];
#pragma unroll
    for (int k = 0; k < 9; ++k) { na[k] = 0.f; nb[k] = 0.f; }

    for (int t0 = beg; t0 < end; t0 += 16) {
        int vcnt = min(16, end - t0);

        // SH for this tile (lanes 0..15, one row each; zero-pad invalid rows)
        if (lane < 16) {
            float* o = wSh + lane * 12;
            if (lane < vcnt) {
                int e = g_csr[t0 + lane];
                float x = evec[(size_t)e * 3], y = evec[(size_t)e * 3 + 1],
                      z = evec[(size_t)e * 3 + 2];
                float rn = rsqrtf(x * x + y * y + z * z);
                x *= rn; y *= rn; z *= rn;
                const float c3  = 1.7320508075688772f;
                const float c15 = 3.872983346207417f;
                const float c5h = 1.118033988749895f;
                const float c15h= 1.9364916731037085f;
                o[0] = 1.f;
                o[1] = c3 * x; o[2] = c3 * y; o[3] = c3 * z;
                o[4] = c15 * x * y; o[5] = c15 * y * z;
                o[6] = c5h * (3.f * z * z - 1.f);
                o[7] = c15 * x * z; o[8] = c15h * (x * x - y * y);
            } else {
#pragma unroll
                for (int k = 0; k < 9; ++k) o[k] = 0.f;
            }
        }
        __syncwarp();

        // L1 A-fragments straight from rad (rows gid, gid+8; cols tid4, tid4+4)
        int p0 = t0 + gid, p1 = t0 + gid + 8;
        bool v0 = p0 < end, v1 = p1 < end;
        int e0 = v0 ? g_csr[p0] : 0;
        int e1 = v1 ? g_csr[p1] : 0;
        int s0r = v0 ? g_send[p0] : 0;
        int s1r = v1 ? g_send[p1] : 0;
        uint32_t r0 = v0 ? f2tf32(__ldg(rad + (size_t)e0 * 8 + tid4)) : 0u;
        uint32_t r1 = v1 ? f2tf32(__ldg(rad + (size_t)e1 * 8 + tid4)) : 0u;
        uint32_t r2 = v0 ? f2tf32(__ldg(rad + (size_t)e0 * 8 + tid4 + 4)) : 0u;
        uint32_t r3 = v1 ? f2tf32(__ldg(rad + (size_t)e1 * 8 + tid4 + 4)) : 0u;

        float acc[8][4];
        uint32_t A0[8], A1[8], A2[8], A3[8];

        // L1: [16,8]@[8,64]
#pragma unroll
        for (int j = 0; j < 8; ++j) {
            acc[j][0] = 0.f; acc[j][1] = 0.f; acc[j][2] = 0.f; acc[j][3] = 0.f;
        }
#pragma unroll
        for (int j = 0; j < 8; ++j) {
            uint2 b = __ldg(&g_wfrag[U_W1 + j * 32 + lane]);
            mma_tf32(acc[j], r0, r1, r2, r3, b.x, b.y);
        }
        cvt_frag(acc, 0.35355339059327373f, A0, A1, A2, A3, lane, tid4);

        layer64(U_W2, A0, A1, A2, A3, acc, lane);
        cvt_frag(acc, 0.125f, A0, A1, A2, A3, lane, tid4);

        layer64(U_W3, A0, A1, A2, A3, acc, lane);
        cvt_frag(acc, 0.125f, A0, A1, A2, A3, lane, tid4);

        l4_chunk<1, 0>(U_W4 + 0 * 2048, A0, A1, A2, A3, s0r, s1r,
                       wMsg, wSh, na, nb, lane, gid, tid4, vcnt);
        l4_chunk<3, 1>(U_W4 + 1 * 2048, A0, A1, A2, A3, s0r, s1r,
                       wMsg, wSh, na, nb, lane, gid, tid4, vcnt);
        l4_chunk<5, 4>(U_W4 + 2 * 2048, A0, A1, A2, A3, s0r, s1r,
                       wMsg, wSh, na, nb, lane, gid, tid4, vcnt);
    }

    // single plain store per node (no atomics)
#pragma unroll
    for (int k = 0; k < 9; ++k) {
        g_agg[(size_t)(n * 9 + k) * 64 + lane]      = na[k];
        g_agg[(size_t)(n * 9 + k) * 64 + 32 + lane] = nb[k];
    }
}

// ---------------- launch 5: linear_down, 16 nodes/block ----------------
template <int D, int KOFF, int OFF>
__device__ __forceinline__ void down_part(const float* __restrict__ sAg,
                                          const float* __restrict__ wrow,
                                          float* __restrict__ outn, int dch) {
    float acc[D];
#pragma unroll
    for (int m = 0; m < D; ++m) acc[m] = 0.f;
#pragma unroll
    for (int c4 = 0; c4 < 16; ++c4) {
        float4 w = *(const float4*)(wrow + c4 * 4);
#pragma unroll
        for (int m = 0; m < D; ++m) {
            float4 a = *(const float4*)(sAg + (KOFF + m) * 64 + c4 * 4);
            acc[m] += a.x * w.x + a.y * w.y + a.z * w.z + a.w * w.w;
        }
    }
#pragma unroll
    for (int m = 0; m < D; ++m)
        outn[OFF + dch * D + m] = acc[m] * 0.125f;
}

__global__ __launch_bounds__(256) void k_down(const float* __restrict__ Wd,
                                              float* __restrict__ out) {
    extern __shared__ float smf[];
    float* sWt = smf;                 // [192][68] = 13056
    float* sAg = smf + 13056;         // 16*576 = 9216
    int t = threadIdx.x;
    for (int idx = t; idx < 3 * 4096; idx += 256) {
        int l = idx >> 12, rem = idx & 4095, c = rem >> 6, dch = rem & 63;
        sWt[(l * 64 + dch) * 68 + c] = Wd[idx];
    }
    int nb = blockIdx.x * 16;
    const float4* aggb = (const float4*)(g_agg + (size_t)nb * 576);
    for (int idx = t; idx < 2304; idx += 256)        // 16*576/4
        ((float4*)sAg)[idx] = aggb[idx];
    __syncthreads();
    if (t < 192) {
        int l = t >> 6, dch = t & 63;
        const float* wrow = sWt + t * 68;
#pragma unroll 1
        for (int i = 0; i < 16; ++i) {
            const float* ag = sAg + i * 576;
            float* outn = out + (size_t)(nb + i) * 576;
            if (l == 0)      down_part<1, 0, 0>(ag, wrow, outn, dch);
            else if (l == 1) down_part<3, 1, 64>(ag, wrow, outn, dch);
            else             down_part<5, 4, 256>(ag, wrow, outn, dch);
        }
    }
}

// ---------------- launch ----------------
extern "C" void kernel_launch(void* const* d_in, const int* in_sizes, int n_in,
                              void* d_out, int out_size) {
    const float* evec = (const float*)d_in[0];
    const float* nf   = (const float*)d_in[1];
    const float* rad  = (const float*)d_in[2];
    const int* senders   = (const int*)d_in[3];
    const int* receivers = (const int*)d_in[4];
    const float* Wup = (const float*)d_in[5];
    const float* W1  = (const float*)d_in[6];
    const float* W2  = (const float*)d_in[7];
    const float* W3  = (const float*)d_in[8];
    const float* W4  = (const float*)d_in[9];
    const float* Wd  = (const float*)d_in[10];
    float* out = (float*)d_out;

    const int SMEM_DOWN = (13056 + 9216) * 4;         // 89088 B
    cudaFuncSetAttribute(k_down, cudaFuncAttributeMaxDynamicSharedMemorySize, SMEM_DOWN);

    k_prep<<<41, 256>>>(W1, W2, W3, W4);
    k_count_h<<<N_EDGES / 256, 256>>>(receivers, nf, Wup);
    k_scan<<<1, 1024>>>();
    k_fill<<<N_EDGES / 256, 256>>>(receivers, senders);
    k_edge<<<N_NODES / 8, 256>>>(evec, rad);
    k_down<<<N_NODES / 16, 256, SMEM_DOWN>>>(Wd, out);
}

// round 9
// speedup vs baseline: 1.4667x; 1.4667x over previous
#include <cuda_runtime.h>
#include <cstdint>

#define N_NODES 10000
#define N_EDGES 320000

// ---------------- scratch (device globals; allocation-free) ----------------
__device__ float g_h[N_NODES * 64];                 // 2.56 MB
__device__ float g_agg[(size_t)N_NODES * 576];      // 23 MB; zeroed by k_down after read
__device__ int   g_count[N_NODES];                  // zeroed by k_scan after read
__device__ int   g_rowstart[N_NODES + 1];
__device__ int   g_cursor[N_NODES];
__device__ int   g_csr[N_EDGES];
__device__ int   g_send[N_EDGES];
__device__ int   g_recv[N_EDGES];
__device__ uint4 g_wfrag[5248];                     // fragment-ordered tf32 weights (84KB)

// uint4 offsets into g_wfrag
#define U_W1 0
#define U_W2 128
#define U_W3 1152
#define U_W4 2176       // + chunk*1024

__device__ __forceinline__ float silu_f(float x) {
    return __fdividef(x, 1.f + __expf(-x));
}

__device__ __forceinline__ uint32_t f2tf32(float f) {
    uint32_t r;
    asm("cvt.rna.tf32.f32 %0, %1;" : "=r"(r) : "f"(f));
    return r;
}

__device__ __forceinline__ void mma_tf32(float acc[4], uint32_t a0, uint32_t a1,
                                         uint32_t a2, uint32_t a3,
                                         uint32_t b0, uint32_t b1) {
    asm volatile(
        "mma.sync.aligned.m16n8k8.row.col.f32.tf32.tf32.f32 "
        "{%0,%1,%2,%3}, {%4,%5,%6,%7}, {%8,%9}, {%0,%1,%2,%3};\n"
        : "+f"(acc[0]), "+f"(acc[1]), "+f"(acc[2]), "+f"(acc[3])
        : "r"(a0), "r"(a1), "r"(a2), "r"(a3), "r"(b0), "r"(b1));
}

// ---------------- launch 0: pre-convert weights into fragment order (uint4) ----------------
// uint4 entry: { tf32 W[k0][n0], tf32 W[k0+4][n0], tf32 W[k0][n1], tf32 W[k0+4][n1] }
// n0 = co + hb*32 + 2*np*8 + (lane>>2), n1 = n0 + 8, k0 = kk*8 + (lane&3).
// Entry index within region: ((hb*2KK + kk*2 + np) ... ) -> local = (((hb*KK + kk)*2 + np)*32 + lane)
__global__ void k_prep(const float* __restrict__ W1, const float* __restrict__ W2,
                       const float* __restrict__ W3, const float* __restrict__ W4) {
    int u = blockIdx.x * 256 + threadIdx.x;
    if (u >= 5248) return;
    const float* src; int rs, co, KK, local;
    if (u < 128)       { src = W1; rs = 64;  co = 0;   KK = 1; local = u; }
    else if (u < 1152) { src = W2; rs = 64;  co = 0;   KK = 8; local = u - 128; }
    else if (u < 2176) { src = W3; rs = 64;  co = 0;   KK = 8; local = u - 1152; }
    else if (u < 3200) { src = W4; rs = 192; co = 0;   KK = 8; local = u - 2176; }
    else if (u < 4224) { src = W4; rs = 192; co = 64;  KK = 8; local = u - 3200; }
    else               { src = W4; rs = 192; co = 128; KK = 8; local = u - 4224; }
    int lane = local & 31; int rest = local >> 5;
    int np = rest & 1; rest >>= 1;
    int kk = rest % KK; int hb = rest / KK;
    int n0 = co + hb * 32 + np * 16 + (lane >> 2);
    int n1 = n0 + 8;
    int k0 = kk * 8 + (lane & 3);
    g_wfrag[u] = make_uint4(f2tf32(src[(size_t)k0 * rs + n0]),
                            f2tf32(src[(size_t)(k0 + 4) * rs + n0]),
                            f2tf32(src[(size_t)k0 * rs + n1]),
                            f2tf32(src[(size_t)(k0 + 4) * rs + n1]));
}

// ---------------- launch 1: edge count histogram + h = (nf @ W_up)/8 ----------------
__global__ __launch_bounds__(256) void k_count_h(const int* __restrict__ recv,
                                                 const float* __restrict__ nf,
                                                 const float* __restrict__ Wup) {
    __shared__ float sW[64 * 64];
    __shared__ float sN[8 * 64];
    int t = threadIdx.x;
    int e = blockIdx.x * 256 + t;
    atomicAdd(&g_count[recv[e]], 1);          // N_EDGES % 256 == 0

    for (int idx = t; idx < 1024; idx += 256)
        ((float4*)sW)[idx] = ((const float4*)Wup)[idx];
    int n0 = blockIdx.x * 8;                  // 1250 * 8 = 10000
    if (t < 128)
        ((float4*)sN)[t] = ((const float4*)(nf + (size_t)n0 * 64))[t];
    __syncthreads();

#pragma unroll
    for (int j = 0; j < 2; ++j) {
        int o = t + j * 256;
        int row = o >> 6, c = o & 63;
        float a0 = 0.f, a1 = 0.f;
#pragma unroll
        for (int k = 0; k < 64; k += 2) {
            a0 = fmaf(sN[row * 64 + k],     sW[k * 64 + c],       a0);
            a1 = fmaf(sN[row * 64 + k + 1], sW[(k + 1) * 64 + c], a1);
        }
        g_h[(size_t)(n0 + row) * 64 + c] = (a0 + a1) * 0.125f;
    }
}

// ---------------- launch 2: parallel exclusive scan (+ zero g_count) ----------------
__global__ __launch_bounds__(1024) void k_scan() {
    __shared__ int warpsum[32];
    int t = threadIdx.x, lane = t & 31, w = t >> 5;
    int base = t * 10;
    int c[10];
    int s = 0;
#pragma unroll
    for (int i = 0; i < 10; ++i) {
        int idx = base + i;
        c[i] = (idx < N_NODES) ? g_count[idx] : 0;
        s += c[i];
    }
    int pre = s;
#pragma unroll
    for (int d = 1; d < 32; d <<= 1) {
        int v = __shfl_up_sync(0xffffffffu, pre, d);
        if (lane >= d) pre += v;
    }
    if (lane == 31) warpsum[w] = pre;
    __syncthreads();
    if (w == 0) {
        int v = warpsum[lane];
#pragma unroll
        for (int d = 1; d < 32; d <<= 1) {
            int u = __shfl_up_sync(0xffffffffu, v, d);
            if (lane >= d) v += u;
        }
        warpsum[lane] = v;
    }
    __syncthreads();
    int wbase = (w > 0) ? warpsum[w - 1] : 0;
    int run = wbase + pre - s;
#pragma unroll
    for (int i = 0; i < 10; ++i) {
        int idx = base + i;
        if (idx < N_NODES) {
            g_rowstart[idx] = run;
            g_cursor[idx] = run;
            run += c[i];
            g_count[idx] = 0;
        }
    }
    if (t == 1023) g_rowstart[N_NODES] = warpsum[31];
}

// ---------------- launch 3: CSR fill ----------------
__global__ void k_fill(const int* __restrict__ recv, const int* __restrict__ send) {
    int e = blockIdx.x * blockDim.x + threadIdx.x;
    if (e < N_EDGES) {
        int r = recv[e];
        int pos = atomicAdd(&g_cursor[r], 1);
        g_csr[pos] = e;
        g_send[pos] = send[e];
        g_recv[pos] = r;
    }
}

// ---------------- launch 4: warp-autonomous fused MLP + SH + TP + scatter ----------------
// Each warp owns 16 CSR positions end-to-end; activations in registers between
// layers (C-frag -> A-frag shuffle conversion); weights streamed as uint4.

__device__ __forceinline__ void layer64(int base, const uint32_t A0[8],
                                        const uint32_t A1[8], const uint32_t A2[8],
                                        const uint32_t A3[8], float acc[8][4],
                                        int lane) {
#pragma unroll
    for (int j = 0; j < 8; ++j) {
        acc[j][0] = 0.f; acc[j][1] = 0.f; acc[j][2] = 0.f; acc[j][3] = 0.f;
    }
#pragma unroll
    for (int kk = 0; kk < 8; ++kk) {
#pragma unroll
        for (int hb = 0; hb < 2; ++hb) {
#pragma unroll
            for (int np = 0; np < 2; ++np) {
                uint4 b = __ldg(&g_wfrag[base + (((hb * 8 + kk) * 2 + np) * 32) + lane]);
                int j = hb * 4 + np * 2;
                mma_tf32(acc[j],     A0[kk], A1[kk], A2[kk], A3[kk], b.x, b.y);
                mma_tf32(acc[j + 1], A0[kk], A1[kk], A2[kk], A3[kk], b.z, b.w);
            }
        }
    }
}

// C-frag -> next layer A-frag conversion (scale + silu + tf32), via shuffles.
__device__ __forceinline__ void cvt_frag(const float acc[8][4], float scale,
                                         uint32_t A0[8], uint32_t A1[8],
                                         uint32_t A2[8], uint32_t A3[8],
                                         int lane, int tid4) {
    int src  = (lane & 28) | (tid4 >> 1);
    int src2 = src + 2;
    bool odd = (tid4 & 1);
#pragma unroll
    for (int j = 0; j < 8; ++j) {
        uint32_t c0 = f2tf32(silu_f(acc[j][0] * scale));
        uint32_t c1 = f2tf32(silu_f(acc[j][1] * scale));
        uint32_t c2 = f2tf32(silu_f(acc[j][2] * scale));
        uint32_t c3 = f2tf32(silu_f(acc[j][3] * scale));
        uint32_t s0 = __shfl_sync(0xffffffffu, c0, src);
        uint32_t s1 = __shfl_sync(0xffffffffu, c1, src);
        uint32_t s2 = __shfl_sync(0xffffffffu, c2, src);
        uint32_t s3 = __shfl_sync(0xffffffffu, c3, src);
        uint32_t u0 = __shfl_sync(0xffffffffu, c0, src2);
        uint32_t u1 = __shfl_sync(0xffffffffu, c1, src2);
        uint32_t u2 = __shfl_sync(0xffffffffu, c2, src2);
        uint32_t u3 = __shfl_sync(0xffffffffu, c3, src2);
        A0[j] = odd ? s1 : s0;
        A1[j] = odd ? s3 : s2;
        A2[j] = odd ? u1 : u0;
        A3[j] = odd ? u3 : u2;
    }
}

template <int D, int KOFF>
__device__ __forceinline__ void l4_chunk(int base, const uint32_t A0[8],
                                         const uint32_t A1[8], const uint32_t A2[8],
                                         const uint32_t A3[8],
                                         const float2 hf0[8], const float2 hf1[8],
                                         float* __restrict__ wMsg,
                                         const float* __restrict__ wSh,
                                         const int* __restrict__ wRecv,
                                         int lane, int gid, int tid4) {
    float acc[8][4];
    layer64(base, A0, A1, A2, A3, acc, lane);

    const float S = 1.f / 256.f;   // 1/sqrt(64) / avg_neigh
#pragma unroll
    for (int j = 0; j < 8; ++j) {
        int col = j * 8 + 2 * tid4;
        *(float2*)(wMsg + gid * 66 + col) =
            make_float2(acc[j][0] * hf0[j].x * S, acc[j][1] * hf0[j].y * S);
        *(float2*)(wMsg + (gid + 8) * 66 + col) =
            make_float2(acc[j][2] * hf1[j].x * S, acc[j][3] * hf1[j].y * S);
    }
    __syncwarp();

    // warp-local segment reduction: lane handles channels (lane) and (lane+32)
    {
        int ncur = wRecv[0];
        float a[D], b[D];
#pragma unroll
        for (int k = 0; k < D; ++k) { a[k] = 0.f; b[k] = 0.f; }
#pragma unroll 4
        for (int r = 0; r < 16; ++r) {
            int n = wRecv[r];
            if (n != ncur) {
#pragma unroll
                for (int k = 0; k < D; ++k) {
                    atomicAdd(&g_agg[(size_t)(ncur * 9 + KOFF + k) * 64 + lane], a[k]);
                    atomicAdd(&g_agg[(size_t)(ncur * 9 + KOFF + k) * 64 + 32 + lane], b[k]);
                    a[k] = 0.f; b[k] = 0.f;
                }
                ncur = n;
            }
            float m0 = wMsg[r * 66 + lane];
            float m1 = wMsg[r * 66 + 32 + lane];
#pragma unroll
            for (int k = 0; k < D; ++k) {
                float s = wSh[r * 12 + KOFF + k];
                a[k] = fmaf(m0, s, a[k]);
                b[k] = fmaf(m1, s, b[k]);
            }
        }
#pragma unroll
        for (int k = 0; k < D; ++k) {
            atomicAdd(&g_agg[(size_t)(ncur * 9 + KOFF + k) * 64 + lane], a[k]);
            atomicAdd(&g_agg[(size_t)(ncur * 9 + KOFF + k) * 64 + 32 + lane], b[k]);
        }
    }
    __syncwarp();
}

__global__ __launch_bounds__(256, 2) void k_edge(const float* __restrict__ evec,
                                                 const float* __restrict__ rad) {
    __shared__ float sMsgAll[8][16 * 66];     // 33792 B
    __shared__ float sShAll[8][16 * 12];      // 6144 B
    __shared__ int   sMeta[8][32];            // 1024 B

    int t = threadIdx.x, lane = t & 31, warp = t >> 5;
    int gid = lane >> 2, tid4 = lane & 3;
    float* wMsg = sMsgAll[warp];
    float* wSh  = sShAll[warp];
    int* wRecv  = sMeta[warp];
    int* wSend  = sMeta[warp] + 16;
    int pos0 = blockIdx.x * 128 + warp * 16;

    // init: lanes 0..15 handle one row each (SH + meta)
    if (lane < 16) {
        int pos = pos0 + lane;
        int e = g_csr[pos];
        wRecv[lane] = g_recv[pos];
        wSend[lane] = g_send[pos];
        float x = evec[(size_t)e * 3], y = evec[(size_t)e * 3 + 1],
              z = evec[(size_t)e * 3 + 2];
        float rn = rsqrtf(x * x + y * y + z * z);
        x *= rn; y *= rn; z *= rn;
        const float c3  = 1.7320508075688772f;
        const float c15 = 3.872983346207417f;
        const float c5h = 1.118033988749895f;
        const float c15h= 1.9364916731037085f;
        float* o = wSh + lane * 12;
        o[0] = 1.f;
        o[1] = c3 * x; o[2] = c3 * y; o[3] = c3 * z;
        o[4] = c15 * x * y; o[5] = c15 * y * z;
        o[6] = c5h * (3.f * z * z - 1.f);
        o[7] = c15 * x * z; o[8] = c15h * (x * x - y * y);
    }
    __syncwarp();

    // L1 A-fragments straight from rad (rows gid, gid+8; cols tid4, tid4+4)
    int e0 = g_csr[pos0 + gid], e1 = g_csr[pos0 + gid + 8];
    uint32_t r0 = f2tf32(__ldg(rad + (size_t)e0 * 8 + tid4));
    uint32_t r1 = f2tf32(__ldg(rad + (size_t)e1 * 8 + tid4));
    uint32_t r2 = f2tf32(__ldg(rad + (size_t)e0 * 8 + tid4 + 4));
    uint32_t r3 = f2tf32(__ldg(rad + (size_t)e1 * 8 + tid4 + 4));

    float acc[8][4];
    uint32_t A0[8], A1[8], A2[8], A3[8];

    // L1: [16,8]@[8,64] — 4 uint4 weight loads
#pragma unroll
    for (int j = 0; j < 8; ++j) {
        acc[j][0] = 0.f; acc[j][1] = 0.f; acc[j][2] = 0.f; acc[j][3] = 0.f;
    }
#pragma unroll
    for (int hb = 0; hb < 2; ++hb)
#pragma unroll
        for (int np = 0; np < 2; ++np) {
            uint4 b = __ldg(&g_wfrag[U_W1 + ((hb * 2 + np) * 32) + lane]);
            int j = hb * 4 + np * 2;
            mma_tf32(acc[j],     r0, r1, r2, r3, b.x, b.y);
            mma_tf32(acc[j + 1], r0, r1, r2, r3, b.z, b.w);
        }
    cvt_frag(acc, 0.35355339059327373f, A0, A1, A2, A3, lane, tid4);

    // L2
    layer64(U_W2, A0, A1, A2, A3, acc, lane);
    cvt_frag(acc, 0.125f, A0, A1, A2, A3, lane, tid4);

    // L3
    layer64(U_W3, A0, A1, A2, A3, acc, lane);
    cvt_frag(acc, 0.125f, A0, A1, A2, A3, lane, tid4);

    // h fragments (register-resident across all 3 chunks)
    int s0r = wSend[gid], s1r = wSend[gid + 8];
    float2 hf0[8], hf1[8];
#pragma unroll
    for (int j = 0; j < 8; ++j) {
        hf0[j] = *(const float2*)(g_h + (size_t)s0r * 64 + j * 8 + 2 * tid4);
        hf1[j] = *(const float2*)(g_h + (size_t)s1r * 64 + j * 8 + 2 * tid4);
    }

    // L4 chunks + tensor product + warp-local segment scatter
    l4_chunk<1, 0>(U_W4 + 0 * 1024, A0, A1, A2, A3, hf0, hf1,
                   wMsg, wSh, wRecv, lane, gid, tid4);
    l4_chunk<3, 1>(U_W4 + 1 * 1024, A0, A1, A2, A3, hf0, hf1,
                   wMsg, wSh, wRecv, lane, gid, tid4);
    l4_chunk<5, 4>(U_W4 + 2 * 1024, A0, A1, A2, A3, hf0, hf1,
                   wMsg, wSh, wRecv, lane, gid, tid4);
}

// ---------------- launch 5: linear_down, 16 nodes/block (also re-zeroes g_agg) ----------------
template <int D, int KOFF, int OFF>
__device__ __forceinline__ void down_part(const float* __restrict__ sAg,
                                          const float* __restrict__ wrow,
                                          float* __restrict__ outn, int dch) {
    float acc[D];
#pragma unroll
    for (int m = 0; m < D; ++m) acc[m] = 0.f;
#pragma unroll
    for (int c4 = 0; c4 < 16; ++c4) {
        float4 w = *(const float4*)(wrow + c4 * 4);
#pragma unroll
        for (int m = 0; m < D; ++m) {
            float4 a = *(const float4*)(sAg + (KOFF + m) * 64 + c4 * 4);
            acc[m] += a.x * w.x + a.y * w.y + a.z * w.z + a.w * w.w;
        }
    }
#pragma unroll
    for (int m = 0; m < D; ++m)
        outn[OFF + dch * D + m] = acc[m] * 0.125f;
}

__global__ __launch_bounds__(256) void k_down(const float* __restrict__ Wd,
                                              float* __restrict__ out) {
    extern __shared__ float smf[];
    float* sWt = smf;                 // [192][68] = 13056
    float* sAg = smf + 13056;         // 16*576 = 9216
    int t = threadIdx.x;
    for (int idx = t; idx < 3 * 4096; idx += 256) {
        int l = idx >> 12, rem = idx & 4095, c = rem >> 6, dch = rem & 63;
        sWt[(l * 64 + dch) * 68 + c] = Wd[idx];
    }
    int nb = blockIdx.x * 16;
    float4* aggb = (float4*)(g_agg + (size_t)nb * 576);
    for (int idx = t; idx < 2304; idx += 256) {      // 16*576/4
        ((float4*)sAg)[idx] = aggb[idx];
        aggb[idx] = make_float4(0.f, 0.f, 0.f, 0.f); // restore invariant
    }
    __syncthreads();
    if (t < 192) {
        int l = t >> 6, dch = t & 63;
        const float* wrow = sWt + t * 68;
#pragma unroll 1
        for (int i = 0; i < 16; ++i) {
            const float* ag = sAg + i * 576;
            float* outn = out + (size_t)(nb + i) * 576;
            if (l == 0)      down_part<1, 0, 0>(ag, wrow, outn, dch);
            else if (l == 1) down_part<3, 1, 64>(ag, wrow, outn, dch);
            else             down_part<5, 4, 256>(ag, wrow, outn, dch);
        }
    }
}

// ---------------- launch ----------------
extern "C" void kernel_launch(void* const* d_in, const int* in_sizes, int n_in,
                              void* d_out, int out_size) {
    const float* evec = (const float*)d_in[0];
    const float* nf   = (const float*)d_in[1];
    const float* rad  = (const float*)d_in[2];
    const int* senders   = (const int*)d_in[3];
    const int* receivers = (const int*)d_in[4];
    const float* Wup = (const float*)d_in[5];
    const float* W1  = (const float*)d_in[6];
    const float* W2  = (const float*)d_in[7];
    const float* W3  = (const float*)d_in[8];
    const float* W4  = (const float*)d_in[9];
    const float* Wd  = (const float*)d_in[10];
    float* out = (float*)d_out;

    const int SMEM_DOWN = (13056 + 9216) * 4;         // 89088 B
    cudaFuncSetAttribute(k_down, cudaFuncAttributeMaxDynamicSharedMemorySize, SMEM_DOWN);

    k_prep<<<21, 256>>>(W1, W2, W3, W4);
    k_count_h<<<N_EDGES / 256, 256>>>(receivers, nf, Wup);
    k_scan<<<1, 1024>>>();
    k_fill<<<N_EDGES / 256, 256>>>(receivers, senders);
    k_edge<<<N_EDGES / 128, 256>>>(evec, rad);
    k_down<<<N_NODES / 16, 256, SMEM_DOWN>>>(Wd, out);
}